// round 1
// baseline (speedup 1.0000x reference)
#include <cuda_runtime.h>
#include <cuda_bf16.h>
#include <math.h>

// Problem constants (fixed shapes)
#define BB   64
#define NN   2048
#define DD   512
#define KK   64
#define GG   16
#define CC   80            // K + G
#define MROWS (BB * NN)    // 131072

// ------------------------- scratch (static device memory) -------------------------
__device__ float g_a[(size_t)MROWS * CC];        // logits -> assignment (in place), 41.9 MB
__device__ float g_v[(size_t)BB * KK * DD];      // vlad raw / residual, 8.4 MB
__device__ float g_colsum[CC];
__device__ float g_colsumsq[CC];
__device__ float g_asum[BB * KK];
__device__ float g_S[BB * KK];
__device__ float g_f[BB * KK];

// ------------------------- K0: zero accumulators (must rerun each launch) ----------
__global__ void k0_zero() {
    int t = blockIdx.x * blockDim.x + threadIdx.x;
    if (t < CC) { g_colsum[t] = 0.f; g_colsumsq[t] = 0.f; }
    if (t < BB * KK) g_asum[t] = 0.f;
}

// ------------------------- K1: a = x @ clusters  (+ BN partial stats) --------------
// block: 128 rows x 80 cols, 256 threads, thread tile 8x5, K-chunks of 32
__global__ __launch_bounds__(256) void k1_gemm1(const float* __restrict__ x,
                                                const float* __restrict__ cl) {
    __shared__ float Xs[32][129];   // [k][row]
    __shared__ float Ws[32][81];    // [k][col]
    __shared__ float s_sum[CC], s_sq[CC];

    const int tid = threadIdx.x;
    const int row0 = blockIdx.x * 128;
    const int rg = tid >> 4;        // 0..15  (8 rows each)
    const int cg = tid & 15;        // 0..15  (5 cols each)

    float acc[8][5];
#pragma unroll
    for (int i = 0; i < 8; ++i)
#pragma unroll
        for (int j = 0; j < 5; ++j) acc[i][j] = 0.f;

    if (tid < CC) { s_sum[tid] = 0.f; s_sq[tid] = 0.f; }

    for (int kc = 0; kc < DD; kc += 32) {
        // load X tile (128 rows x 32 k) transposed into Xs[k][row]
#pragma unroll
        for (int it = 0; it < 4; ++it) {
            int f  = tid + it * 256;          // 0..1023 float4s
            int r  = f >> 3;
            int c4 = f & 7;
            float4 v = *(const float4*)(x + (size_t)(row0 + r) * DD + kc + c4 * 4);
            Xs[c4 * 4 + 0][r] = v.x;
            Xs[c4 * 4 + 1][r] = v.y;
            Xs[c4 * 4 + 2][r] = v.z;
            Xs[c4 * 4 + 3][r] = v.w;
        }
        // load W tile (32 k x 80 cols)
#pragma unroll
        for (int it = 0; it < 10; ++it) {
            int f = tid + it * 256;           // 0..2559
            int r = f / CC;
            int c = f - r * CC;
            Ws[r][c] = cl[(size_t)(kc + r) * CC + c];
        }
        __syncthreads();

#pragma unroll
        for (int k = 0; k < 32; ++k) {
            float xf[8], wf[5];
#pragma unroll
            for (int i = 0; i < 8; ++i) xf[i] = Xs[k][rg * 8 + i];
#pragma unroll
            for (int j = 0; j < 5; ++j) wf[j] = Ws[k][cg * 5 + j];
#pragma unroll
            for (int i = 0; i < 8; ++i)
#pragma unroll
                for (int j = 0; j < 5; ++j) acc[i][j] += xf[i] * wf[j];
        }
        __syncthreads();
    }

    // write logits
#pragma unroll
    for (int i = 0; i < 8; ++i) {
        size_t base = (size_t)(row0 + rg * 8 + i) * CC + cg * 5;
#pragma unroll
        for (int j = 0; j < 5; ++j) g_a[base + j] = acc[i][j];
    }
    // partial BN stats
#pragma unroll
    for (int j = 0; j < 5; ++j) {
        float s = 0.f, q = 0.f;
#pragma unroll
        for (int i = 0; i < 8; ++i) { s += acc[i][j]; q += acc[i][j] * acc[i][j]; }
        atomicAdd(&s_sum[cg * 5 + j], s);
        atomicAdd(&s_sq [cg * 5 + j], q);
    }
    __syncthreads();
    if (tid < CC) {
        atomicAdd(&g_colsum[tid],   s_sum[tid]);
        atomicAdd(&g_colsumsq[tid], s_sq[tid]);
    }
}

// ------------------------- K2: BN + softmax + assignment + a_sum -------------------
// block handles 128 contiguous rows (16 blocks per batch); one warp per 16 rows
__global__ __launch_bounds__(256) void k2_softmax(const float* __restrict__ bnw,
                                                  const float* __restrict__ bnb) {
    __shared__ float s_scale[CC], s_shift[CC];
    __shared__ float s_asum[KK];

    const int tid  = threadIdx.x;
    const int lane = tid & 31;
    const int w    = tid >> 5;
    const int row0 = blockIdx.x * 128;
    const int batch = blockIdx.x >> 4;   // 16 blocks per batch

    if (tid < CC) {
        const float invM = 1.f / (float)MROWS;
        float m   = g_colsum[tid] * invM;
        float var = g_colsumsq[tid] * invM - m * m;
        float sc  = rsqrtf(var + 1e-5f) * bnw[tid];
        s_scale[tid] = sc;
        s_shift[tid] = bnb[tid] - m * sc;
    }
    if (tid < KK) s_asum[tid] = 0.f;
    __syncthreads();

    const float sc0 = s_scale[lane],      sh0 = s_shift[lane];
    const float sc1 = s_scale[lane + 32], sh1 = s_shift[lane + 32];
    float sc2 = 0.f, sh2 = 0.f;
    if (lane < 16) { sc2 = s_scale[lane + 64]; sh2 = s_shift[lane + 64]; }

    for (int r = 0; r < 16; ++r) {
        const int row = row0 + w * 16 + r;
        const size_t base = (size_t)row * CC;
        float y0 = g_a[base + lane]      * sc0 + sh0;
        float y1 = g_a[base + 32 + lane] * sc1 + sh1;
        float y2 = (lane < 16) ? (g_a[base + 64 + lane] * sc2 + sh2) : -3.4e38f;

        float mx = fmaxf(fmaxf(y0, y1), y2);
#pragma unroll
        for (int o = 16; o > 0; o >>= 1) mx = fmaxf(mx, __shfl_xor_sync(0xffffffffu, mx, o));

        float e0 = expf(y0 - mx);
        float e1 = expf(y1 - mx);
        float e2 = (lane < 16) ? expf(y2 - mx) : 0.f;
        float s  = e0 + e1 + e2;
#pragma unroll
        for (int o = 16; o > 0; o >>= 1) s += __shfl_xor_sync(0xffffffffu, s, o);

        float inv = 1.f / s;
        float p0 = e0 * inv, p1 = e1 * inv;
        g_a[base + lane]      = p0;
        g_a[base + 32 + lane] = p1;
        atomicAdd(&s_asum[lane],      p0);
        atomicAdd(&s_asum[lane + 32], p1);
    }
    __syncthreads();
    if (tid < KK) atomicAdd(&g_asum[batch * KK + tid], s_asum[tid]);
}

// ------------------------- K3: vlad_raw[b,k,d] = sum_n p[b,n,k] x[b,n,d] -----------
// block: one batch b, 128-d tile, 64 k, 256 threads, thread tile 4k x 8d
__global__ __launch_bounds__(256) void k3_gemm2(const float* __restrict__ x) {
    __shared__ float4 Ps4[32][17];   // [n][k/4]
    __shared__ float4 Xs4[32][33];   // [n][d/4]

    const int tid = threadIdx.x;
    const int b   = blockIdx.y;
    const int d0  = blockIdx.x * 128;
    const int kg  = tid >> 4;        // 0..15 (4 k each)
    const int dg  = tid & 15;        // 0..15 (8 d each)

    float acc[4][8];
#pragma unroll
    for (int i = 0; i < 4; ++i)
#pragma unroll
        for (int j = 0; j < 8; ++j) acc[i][j] = 0.f;

    const float* xb = x   + (size_t)b * NN * DD;
    const float* pb = g_a + (size_t)b * NN * CC;

    for (int n0 = 0; n0 < NN; n0 += 32) {
#pragma unroll
        for (int it = 0; it < 2; ++it) {
            int f  = tid + it * 256;      // 0..511
            int n  = f >> 4;
            int c4 = f & 15;
            Ps4[n][c4] = *(const float4*)(pb + (size_t)(n0 + n) * CC + c4 * 4);
        }
#pragma unroll
        for (int it = 0; it < 4; ++it) {
            int f  = tid + it * 256;      // 0..1023
            int n  = f >> 5;
            int c4 = f & 31;
            Xs4[n][c4] = *(const float4*)(xb + (size_t)(n0 + n) * DD + d0 + c4 * 4);
        }
        __syncthreads();

#pragma unroll
        for (int n = 0; n < 32; ++n) {
            float4 p  = Ps4[n][kg];
            float4 xa = Xs4[n][2 * dg];
            float4 xc = Xs4[n][2 * dg + 1];
            float pv[4] = {p.x, p.y, p.z, p.w};
            float xv[8] = {xa.x, xa.y, xa.z, xa.w, xc.x, xc.y, xc.z, xc.w};
#pragma unroll
            for (int i = 0; i < 4; ++i)
#pragma unroll
                for (int j = 0; j < 8; ++j) acc[i][j] += pv[i] * xv[j];
        }
        __syncthreads();
    }

#pragma unroll
    for (int i = 0; i < 4; ++i) {
        size_t rowb = ((size_t)b * KK + kg * 4 + i) * DD + d0 + dg * 8;
        *(float4*)(g_v + rowb)     = make_float4(acc[i][0], acc[i][1], acc[i][2], acc[i][3]);
        *(float4*)(g_v + rowb + 4) = make_float4(acc[i][4], acc[i][5], acc[i][6], acc[i][7]);
    }
}

// ------------------------- K4: residual subtract + per-(b,k) sumsq -----------------
__global__ __launch_bounds__(128) void k4_resid(const float* __restrict__ c2) {
    const int bk  = blockIdx.x;
    const int k   = bk & 63;
    const int tid = threadIdx.x;
    const float asum = g_asum[bk];
    const size_t base = (size_t)bk * DD;
    const int d = tid * 4;

    float4 v = *(const float4*)(g_v + base + d);
    float r0 = v.x - asum * c2[(size_t)(d + 0) * KK + k];
    float r1 = v.y - asum * c2[(size_t)(d + 1) * KK + k];
    float r2 = v.z - asum * c2[(size_t)(d + 2) * KK + k];
    float r3 = v.w - asum * c2[(size_t)(d + 3) * KK + k];
    *(float4*)(g_v + base + d) = make_float4(r0, r1, r2, r3);

    float ss = r0 * r0 + r1 * r1 + r2 * r2 + r3 * r3;
#pragma unroll
    for (int o = 16; o > 0; o >>= 1) ss += __shfl_xor_sync(0xffffffffu, ss, o);
    __shared__ float sh[4];
    if ((tid & 31) == 0) sh[tid >> 5] = ss;
    __syncthreads();
    if (tid == 0) g_S[bk] = sh[0] + sh[1] + sh[2] + sh[3];
}

// ------------------------- K5: per-batch norm factors ------------------------------
__global__ void k5_norm() {
    const int b = blockIdx.x;
    const int k = threadIdx.x;   // 64 threads
    float S    = g_S[b * KK + k];
    float norm = sqrtf(S);
    float inv  = 1.f / fmaxf(norm, 1e-12f);
    float c    = S * inv * inv;
#pragma unroll
    for (int o = 16; o > 0; o >>= 1) c += __shfl_xor_sync(0xffffffffu, c, o);
    __shared__ float sh[2];
    if ((k & 31) == 0) sh[k >> 5] = c;
    __syncthreads();
    float g = sqrtf(sh[0] + sh[1]);
    g_f[b * KK + k] = inv / fmaxf(g, 1e-12f);
}

// ------------------------- K6: scale + transpose write out[b, d*K + k] -------------
__global__ __launch_bounds__(256) void k6_write(float* __restrict__ out) {
    __shared__ float T[64][65];
    __shared__ float s_f[KK];
    const int b  = blockIdx.y;
    const int d0 = blockIdx.x * 64;
    const int tid = threadIdx.x;

    if (tid < KK) s_f[tid] = g_f[b * KK + tid];
    __syncthreads();

#pragma unroll
    for (int it = 0; it < 16; ++it) {
        int idx = tid + it * 256;
        int k  = idx >> 6;
        int dd = idx & 63;
        T[dd][k] = g_v[((size_t)b * KK + k) * DD + d0 + dd] * s_f[k];
    }
    __syncthreads();
#pragma unroll
    for (int it = 0; it < 16; ++it) {
        int idx = tid + it * 256;
        int dd = idx >> 6;
        int k  = idx & 63;
        out[(size_t)b * (DD * KK) + (size_t)(d0 + dd) * KK + k] = T[dd][k];
    }
}

// ------------------------- launch -------------------------------------------------
extern "C" void kernel_launch(void* const* d_in, const int* in_sizes, int n_in,
                              void* d_out, int out_size) {
    const float* x        = (const float*)d_in[0];   // (B, N, D)
    const float* clusters = (const float*)d_in[1];   // (D, K+G)
    const float* clusters2= (const float*)d_in[2];   // (1, D, K)
    const float* bnw      = (const float*)d_in[3];   // (K+G,)
    const float* bnb      = (const float*)d_in[4];   // (K+G,)
    float* out            = (float*)d_out;           // (B, D*K)

    k0_zero   <<<16, 256>>>();
    k1_gemm1  <<<MROWS / 128, 256>>>(x, clusters);
    k2_softmax<<<MROWS / 128, 256>>>(bnw, bnb);
    k3_gemm2  <<<dim3(DD / 128, BB), 256>>>(x);
    k4_resid  <<<BB * KK, 128>>>(clusters2);
    k5_norm   <<<BB, 64>>>();
    k6_write  <<<dim3(DD / 64, BB), 256>>>(out);
}

// round 2
// speedup vs baseline: 1.0843x; 1.0843x over previous
#include <cuda_runtime.h>
#include <cuda_bf16.h>
#include <math.h>

// Problem constants (fixed shapes)
#define BB   64
#define NN   2048
#define DD   512
#define KK   64
#define GG   16
#define CC   80            // K + G
#define MROWS (BB * NN)    // 131072
#define NSPLIT 4           // k3 N-dimension split factor
#define NCHUNK (NN / NSPLIT)

// ------------------------- scratch (static device memory) -------------------------
__device__ float g_a[(size_t)MROWS * CC];                    // logits -> assignment, 41.9 MB
__device__ float g_vp[(size_t)NSPLIT * BB * KK * DD];        // k3 partials, 33.5 MB
__device__ float g_v[(size_t)BB * KK * DD];                  // residual, 8.4 MB
__device__ float g_colsum[CC];
__device__ float g_colsumsq[CC];
__device__ float g_asum[BB * KK];
__device__ float g_S[BB * KK];
__device__ float g_f[BB * KK];

// ------------------------- K0: zero accumulators (must rerun each launch) ----------
__global__ void k0_zero() {
    int t = blockIdx.x * blockDim.x + threadIdx.x;
    if (t < CC) { g_colsum[t] = 0.f; g_colsumsq[t] = 0.f; }
    if (t < BB * KK) g_asum[t] = 0.f;
}

// ------------------------- K1: a = x @ clusters  (+ BN partial stats) --------------
// block: 128 rows x 80 cols, 256 threads, thread tile 8x5, K-chunks of 32
__global__ __launch_bounds__(256) void k1_gemm1(const float* __restrict__ x,
                                                const float* __restrict__ cl) {
    __shared__ float Xs[32][129];   // [k][row]
    __shared__ float Ws[32][81];    // [k][col]
    __shared__ float s_sum[CC], s_sq[CC];

    const int tid = threadIdx.x;
    const int row0 = blockIdx.x * 128;
    const int rg = tid >> 4;        // 0..15  (8 rows each)
    const int cg = tid & 15;        // 0..15  (5 cols each)

    float acc[8][5];
#pragma unroll
    for (int i = 0; i < 8; ++i)
#pragma unroll
        for (int j = 0; j < 5; ++j) acc[i][j] = 0.f;

    if (tid < CC) { s_sum[tid] = 0.f; s_sq[tid] = 0.f; }

    for (int kc = 0; kc < DD; kc += 32) {
        // load X tile (128 rows x 32 k) transposed into Xs[k][row]
#pragma unroll
        for (int it = 0; it < 4; ++it) {
            int f  = tid + it * 256;          // 0..1023 float4s
            int r  = f >> 3;
            int c4 = f & 7;
            float4 v = *(const float4*)(x + (size_t)(row0 + r) * DD + kc + c4 * 4);
            Xs[c4 * 4 + 0][r] = v.x;
            Xs[c4 * 4 + 1][r] = v.y;
            Xs[c4 * 4 + 2][r] = v.z;
            Xs[c4 * 4 + 3][r] = v.w;
        }
        // load W tile (32 k x 80 cols)
#pragma unroll
        for (int it = 0; it < 10; ++it) {
            int f = tid + it * 256;           // 0..2559
            int r = f / CC;
            int c = f - r * CC;
            Ws[r][c] = cl[(size_t)(kc + r) * CC + c];
        }
        __syncthreads();

#pragma unroll
        for (int k = 0; k < 32; ++k) {
            float xf[8], wf[5];
#pragma unroll
            for (int i = 0; i < 8; ++i) xf[i] = Xs[k][rg * 8 + i];
#pragma unroll
            for (int j = 0; j < 5; ++j) wf[j] = Ws[k][cg * 5 + j];
#pragma unroll
            for (int i = 0; i < 8; ++i)
#pragma unroll
                for (int j = 0; j < 5; ++j) acc[i][j] += xf[i] * wf[j];
        }
        __syncthreads();
    }

    // write logits
#pragma unroll
    for (int i = 0; i < 8; ++i) {
        size_t base = (size_t)(row0 + rg * 8 + i) * CC + cg * 5;
#pragma unroll
        for (int j = 0; j < 5; ++j) g_a[base + j] = acc[i][j];
    }
    // partial BN stats
#pragma unroll
    for (int j = 0; j < 5; ++j) {
        float s = 0.f, q = 0.f;
#pragma unroll
        for (int i = 0; i < 8; ++i) { s += acc[i][j]; q += acc[i][j] * acc[i][j]; }
        atomicAdd(&s_sum[cg * 5 + j], s);
        atomicAdd(&s_sq [cg * 5 + j], q);
    }
    __syncthreads();
    if (tid < CC) {
        atomicAdd(&g_colsum[tid],   s_sum[tid]);
        atomicAdd(&g_colsumsq[tid], s_sq[tid]);
    }
}

// ------------------------- K2: BN + softmax + assignment + a_sum -------------------
// block handles 128 contiguous rows (16 blocks per batch); one warp per 16 rows
__global__ __launch_bounds__(256) void k2_softmax(const float* __restrict__ bnw,
                                                  const float* __restrict__ bnb) {
    __shared__ float s_scale[CC], s_shift[CC];
    __shared__ float s_asum[KK];

    const int tid  = threadIdx.x;
    const int lane = tid & 31;
    const int w    = tid >> 5;
    const int row0 = blockIdx.x * 128;
    const int batch = blockIdx.x >> 4;   // 16 blocks per batch

    if (tid < CC) {
        const float invM = 1.f / (float)MROWS;
        float m   = g_colsum[tid] * invM;
        float var = g_colsumsq[tid] * invM - m * m;
        float sc  = rsqrtf(var + 1e-5f) * bnw[tid];
        s_scale[tid] = sc;
        s_shift[tid] = bnb[tid] - m * sc;
    }
    if (tid < KK) s_asum[tid] = 0.f;
    __syncthreads();

    const float sc0 = s_scale[lane],      sh0 = s_shift[lane];
    const float sc1 = s_scale[lane + 32], sh1 = s_shift[lane + 32];
    float sc2 = 0.f, sh2 = 0.f;
    if (lane < 16) { sc2 = s_scale[lane + 64]; sh2 = s_shift[lane + 64]; }

    for (int r = 0; r < 16; ++r) {
        const int row = row0 + w * 16 + r;
        const size_t base = (size_t)row * CC;
        float y0 = g_a[base + lane]      * sc0 + sh0;
        float y1 = g_a[base + 32 + lane] * sc1 + sh1;
        float y2 = (lane < 16) ? (g_a[base + 64 + lane] * sc2 + sh2) : -3.4e38f;

        float mx = fmaxf(fmaxf(y0, y1), y2);
#pragma unroll
        for (int o = 16; o > 0; o >>= 1) mx = fmaxf(mx, __shfl_xor_sync(0xffffffffu, mx, o));

        float e0 = expf(y0 - mx);
        float e1 = expf(y1 - mx);
        float e2 = (lane < 16) ? expf(y2 - mx) : 0.f;
        float s  = e0 + e1 + e2;
#pragma unroll
        for (int o = 16; o > 0; o >>= 1) s += __shfl_xor_sync(0xffffffffu, s, o);

        float inv = 1.f / s;
        float p0 = e0 * inv, p1 = e1 * inv;
        g_a[base + lane]      = p0;
        g_a[base + 32 + lane] = p1;
        atomicAdd(&s_asum[lane],      p0);
        atomicAdd(&s_asum[lane + 32], p1);
    }
    __syncthreads();
    if (tid < KK) atomicAdd(&g_asum[batch * KK + tid], s_asum[tid]);
}

// ------------------------- K3: partial vlad[b,k,d] over an N-chunk ------------------
// block: one batch b, 128-d tile, one of NSPLIT n-chunks; 256 threads, tile 4k x 8d
__global__ __launch_bounds__(256) void k3_gemm2(const float* __restrict__ x) {
    __shared__ float4 Ps4[32][17];   // [n][k/4]
    __shared__ float4 Xs4[32][33];   // [n][d/4]

    const int tid = threadIdx.x;
    const int b   = blockIdx.y;
    const int d0  = blockIdx.x * 128;
    const int z   = blockIdx.z;      // n-chunk
    const int kg  = tid >> 4;        // 0..15 (4 k each)
    const int dg  = tid & 15;        // 0..15 (8 d each)

    float acc[4][8];
#pragma unroll
    for (int i = 0; i < 4; ++i)
#pragma unroll
        for (int j = 0; j < 8; ++j) acc[i][j] = 0.f;

    const float* xb = x   + (size_t)b * NN * DD;
    const float* pb = g_a + (size_t)b * NN * CC;
    const int nbeg = z * NCHUNK;
    const int nend = nbeg + NCHUNK;

    for (int n0 = nbeg; n0 < nend; n0 += 32) {
#pragma unroll
        for (int it = 0; it < 2; ++it) {
            int f  = tid + it * 256;      // 0..511
            int n  = f >> 4;
            int c4 = f & 15;
            Ps4[n][c4] = *(const float4*)(pb + (size_t)(n0 + n) * CC + c4 * 4);
        }
#pragma unroll
        for (int it = 0; it < 4; ++it) {
            int f  = tid + it * 256;      // 0..1023
            int n  = f >> 5;
            int c4 = f & 31;
            Xs4[n][c4] = *(const float4*)(xb + (size_t)(n0 + n) * DD + d0 + c4 * 4);
        }
        __syncthreads();

#pragma unroll
        for (int n = 0; n < 32; ++n) {
            float4 p  = Ps4[n][kg];
            float4 xa = Xs4[n][2 * dg];
            float4 xc = Xs4[n][2 * dg + 1];
            float pv[4] = {p.x, p.y, p.z, p.w};
            float xv[8] = {xa.x, xa.y, xa.z, xa.w, xc.x, xc.y, xc.z, xc.w};
#pragma unroll
            for (int i = 0; i < 4; ++i)
#pragma unroll
                for (int j = 0; j < 8; ++j) acc[i][j] += pv[i] * xv[j];
        }
        __syncthreads();
    }

    float* vp = g_vp + (size_t)z * BB * KK * DD;
#pragma unroll
    for (int i = 0; i < 4; ++i) {
        size_t rowb = ((size_t)b * KK + kg * 4 + i) * DD + d0 + dg * 8;
        *(float4*)(vp + rowb)     = make_float4(acc[i][0], acc[i][1], acc[i][2], acc[i][3]);
        *(float4*)(vp + rowb + 4) = make_float4(acc[i][4], acc[i][5], acc[i][6], acc[i][7]);
    }
}

// ------------------------- K4: sum partials + residual subtract + sumsq ------------
__global__ __launch_bounds__(128) void k4_resid(const float* __restrict__ c2) {
    const int bk  = blockIdx.x;
    const int k   = bk & 63;
    const int tid = threadIdx.x;
    const float asum = g_asum[bk];
    const size_t base = (size_t)bk * DD;
    const int d = tid * 4;
    const size_t stride = (size_t)BB * KK * DD;

    float4 v0 = *(const float4*)(g_vp + 0 * stride + base + d);
    float4 v1 = *(const float4*)(g_vp + 1 * stride + base + d);
    float4 v2 = *(const float4*)(g_vp + 2 * stride + base + d);
    float4 v3 = *(const float4*)(g_vp + 3 * stride + base + d);
    float sx = (v0.x + v1.x) + (v2.x + v3.x);
    float sy = (v0.y + v1.y) + (v2.y + v3.y);
    float sz = (v0.z + v1.z) + (v2.z + v3.z);
    float sw = (v0.w + v1.w) + (v2.w + v3.w);

    float r0 = sx - asum * c2[(size_t)(d + 0) * KK + k];
    float r1 = sy - asum * c2[(size_t)(d + 1) * KK + k];
    float r2 = sz - asum * c2[(size_t)(d + 2) * KK + k];
    float r3 = sw - asum * c2[(size_t)(d + 3) * KK + k];
    *(float4*)(g_v + base + d) = make_float4(r0, r1, r2, r3);

    float ss = r0 * r0 + r1 * r1 + r2 * r2 + r3 * r3;
#pragma unroll
    for (int o = 16; o > 0; o >>= 1) ss += __shfl_xor_sync(0xffffffffu, ss, o);
    __shared__ float sh[4];
    if ((tid & 31) == 0) sh[tid >> 5] = ss;
    __syncthreads();
    if (tid == 0) g_S[bk] = sh[0] + sh[1] + sh[2] + sh[3];
}

// ------------------------- K5: per-batch norm factors ------------------------------
__global__ void k5_norm() {
    const int b = blockIdx.x;
    const int k = threadIdx.x;   // 64 threads
    float S    = g_S[b * KK + k];
    float norm = sqrtf(S);
    float inv  = 1.f / fmaxf(norm, 1e-12f);
    float c    = S * inv * inv;
#pragma unroll
    for (int o = 16; o > 0; o >>= 1) c += __shfl_xor_sync(0xffffffffu, c, o);
    __shared__ float sh[2];
    if ((k & 31) == 0) sh[k >> 5] = c;
    __syncthreads();
    float g = sqrtf(sh[0] + sh[1]);
    g_f[b * KK + k] = inv / fmaxf(g, 1e-12f);
}

// ------------------------- K6: scale + transpose write out[b, d*K + k] -------------
__global__ __launch_bounds__(256) void k6_write(float* __restrict__ out) {
    __shared__ float T[64][65];
    __shared__ float s_f[KK];
    const int b  = blockIdx.y;
    const int d0 = blockIdx.x * 64;
    const int tid = threadIdx.x;

    if (tid < KK) s_f[tid] = g_f[b * KK + tid];
    __syncthreads();

#pragma unroll
    for (int it = 0; it < 16; ++it) {
        int idx = tid + it * 256;
        int k  = idx >> 6;
        int dd = idx & 63;
        T[dd][k] = g_v[((size_t)b * KK + k) * DD + d0 + dd] * s_f[k];
    }
    __syncthreads();
#pragma unroll
    for (int it = 0; it < 16; ++it) {
        int idx = tid + it * 256;
        int dd = idx >> 6;
        int k  = idx & 63;
        out[(size_t)b * (DD * KK) + (size_t)(d0 + dd) * KK + k] = T[dd][k];
    }
}

// ------------------------- launch -------------------------------------------------
extern "C" void kernel_launch(void* const* d_in, const int* in_sizes, int n_in,
                              void* d_out, int out_size) {
    const float* x        = (const float*)d_in[0];   // (B, N, D)
    const float* clusters = (const float*)d_in[1];   // (D, K+G)
    const float* clusters2= (const float*)d_in[2];   // (1, D, K)
    const float* bnw      = (const float*)d_in[3];   // (K+G,)
    const float* bnb      = (const float*)d_in[4];   // (K+G,)
    float* out            = (float*)d_out;           // (B, D*K)

    k0_zero   <<<16, 256>>>();
    k1_gemm1  <<<MROWS / 128, 256>>>(x, clusters);
    k2_softmax<<<MROWS / 128, 256>>>(bnw, bnb);
    k3_gemm2  <<<dim3(DD / 128, BB, NSPLIT), 256>>>(x);
    k4_resid  <<<BB * KK, 128>>>(clusters2);
    k5_norm   <<<BB, 64>>>();
    k6_write  <<<dim3(DD / 64, BB), 256>>>(out);
}

// round 6
// speedup vs baseline: 1.3576x; 1.2521x over previous
#include <cuda_runtime.h>
#include <cuda_bf16.h>
#include <math.h>
#include <cstdint>

// Problem constants (fixed shapes)
#define BB   64
#define NN   2048
#define DD   512
#define KK   64
#define GG   16
#define CC   80            // K + G
#define MROWS (BB * NN)    // 131072

// ------------------------- scratch (static device memory) -------------------------
__device__ float g_a[(size_t)MROWS * CC];        // logits -> assignment (in place)
__device__ float g_v[(size_t)BB * DD * KK];      // vlad, layout [b][d][k]  (8.4 MB)
__device__ float g_colsum[CC];
__device__ float g_colsumsq[CC];
__device__ float g_asum[BB * KK];
__device__ float g_S[BB * KK];
__device__ float g_f[BB * KK];

// ------------------------- warp-MMA helpers (sm_80+ path, works on sm_100) ---------
__device__ __forceinline__ uint32_t smem_u32(const void* p) {
    uint32_t a;
    asm("{ .reg .u64 t; cvta.to.shared.u64 t, %1; cvt.u32.u64 %0, t; }" : "=r"(a) : "l"(p));
    return a;
}

#define LDSM_X4(r0, r1, r2, r3, addr) \
    asm volatile("ldmatrix.sync.aligned.m8n8.x4.shared.b16 {%0,%1,%2,%3}, [%4];" \
                 : "=r"(r0), "=r"(r1), "=r"(r2), "=r"(r3) : "r"(addr))

#define MMA_BF16(d, a, b0, b1) \
    asm volatile("mma.sync.aligned.m16n8k16.row.col.f32.bf16.bf16.f32 " \
                 "{%0,%1,%2,%3}, {%4,%5,%6,%7}, {%8,%9}, {%0,%1,%2,%3};" \
                 : "+f"((d)[0]), "+f"((d)[1]), "+f"((d)[2]), "+f"((d)[3]) \
                 : "r"((a)[0]), "r"((a)[1]), "r"((a)[2]), "r"((a)[3]), \
                   "r"(b0), "r"(b1))

__device__ __forceinline__ void split_bf16(float v, uint16_t& h, uint16_t& l) {
    __nv_bfloat16 bh = __float2bfloat16_rn(v);
    float r = v - __bfloat162float(bh);
    __nv_bfloat16 bl = __float2bfloat16_rn(r);
    h = *reinterpret_cast<uint16_t*>(&bh);
    l = *reinterpret_cast<uint16_t*>(&bl);
}

// ------------------------- K0: zero accumulators -----------------------------------
__global__ void k0_zero() {
    int t = blockIdx.x * blockDim.x + threadIdx.x;
    if (t < CC) { g_colsum[t] = 0.f; g_colsumsq[t] = 0.f; }
    if (t < BB * KK) g_asum[t] = 0.f;
}

// ------------------------- K1: a = x @ clusters  (+ BN partial stats) --------------
__global__ __launch_bounds__(256) void k1_gemm1(const float* __restrict__ x,
                                                const float* __restrict__ cl) {
    __shared__ float Xs[32][129];
    __shared__ float Ws[32][81];
    __shared__ float s_sum[CC], s_sq[CC];

    const int tid = threadIdx.x;
    const int row0 = blockIdx.x * 128;
    const int rg = tid >> 4;
    const int cg = tid & 15;

    float acc[8][5];
#pragma unroll
    for (int i = 0; i < 8; ++i)
#pragma unroll
        for (int j = 0; j < 5; ++j) acc[i][j] = 0.f;

    if (tid < CC) { s_sum[tid] = 0.f; s_sq[tid] = 0.f; }

    for (int kc = 0; kc < DD; kc += 32) {
#pragma unroll
        for (int it = 0; it < 4; ++it) {
            int f  = tid + it * 256;
            int r  = f >> 3;
            int c4 = f & 7;
            float4 v = *(const float4*)(x + (size_t)(row0 + r) * DD + kc + c4 * 4);
            Xs[c4 * 4 + 0][r] = v.x;
            Xs[c4 * 4 + 1][r] = v.y;
            Xs[c4 * 4 + 2][r] = v.z;
            Xs[c4 * 4 + 3][r] = v.w;
        }
#pragma unroll
        for (int it = 0; it < 10; ++it) {
            int f = tid + it * 256;
            int r = f / CC;
            int c = f - r * CC;
            Ws[r][c] = cl[(size_t)(kc + r) * CC + c];
        }
        __syncthreads();

#pragma unroll
        for (int k = 0; k < 32; ++k) {
            float xf[8], wf[5];
#pragma unroll
            for (int i = 0; i < 8; ++i) xf[i] = Xs[k][rg * 8 + i];
#pragma unroll
            for (int j = 0; j < 5; ++j) wf[j] = Ws[k][cg * 5 + j];
#pragma unroll
            for (int i = 0; i < 8; ++i)
#pragma unroll
                for (int j = 0; j < 5; ++j) acc[i][j] += xf[i] * wf[j];
        }
        __syncthreads();
    }

#pragma unroll
    for (int i = 0; i < 8; ++i) {
        size_t base = (size_t)(row0 + rg * 8 + i) * CC + cg * 5;
#pragma unroll
        for (int j = 0; j < 5; ++j) g_a[base + j] = acc[i][j];
    }
#pragma unroll
    for (int j = 0; j < 5; ++j) {
        float s = 0.f, q = 0.f;
#pragma unroll
        for (int i = 0; i < 8; ++i) { s += acc[i][j]; q += acc[i][j] * acc[i][j]; }
        atomicAdd(&s_sum[cg * 5 + j], s);
        atomicAdd(&s_sq [cg * 5 + j], q);
    }
    __syncthreads();
    if (tid < CC) {
        atomicAdd(&g_colsum[tid],   s_sum[tid]);
        atomicAdd(&g_colsumsq[tid], s_sq[tid]);
    }
}

// ------------------------- K2: BN + softmax + assignment + a_sum -------------------
__global__ __launch_bounds__(256) void k2_softmax(const float* __restrict__ bnw,
                                                  const float* __restrict__ bnb) {
    __shared__ float s_scale[CC], s_shift[CC];
    __shared__ float s_asum[KK];

    const int tid  = threadIdx.x;
    const int lane = tid & 31;
    const int w    = tid >> 5;
    const int row0 = blockIdx.x * 128;
    const int batch = blockIdx.x >> 4;

    if (tid < CC) {
        const float invM = 1.f / (float)MROWS;
        float m   = g_colsum[tid] * invM;
        float var = g_colsumsq[tid] * invM - m * m;
        float sc  = rsqrtf(var + 1e-5f) * bnw[tid];
        s_scale[tid] = sc;
        s_shift[tid] = bnb[tid] - m * sc;
    }
    if (tid < KK) s_asum[tid] = 0.f;
    __syncthreads();

    const float sc0 = s_scale[lane],      sh0 = s_shift[lane];
    const float sc1 = s_scale[lane + 32], sh1 = s_shift[lane + 32];
    float sc2 = 0.f, sh2 = 0.f;
    if (lane < 16) { sc2 = s_scale[lane + 64]; sh2 = s_shift[lane + 64]; }

    for (int r = 0; r < 16; ++r) {
        const int row = row0 + w * 16 + r;
        const size_t base = (size_t)row * CC;
        float y0 = g_a[base + lane]      * sc0 + sh0;
        float y1 = g_a[base + 32 + lane] * sc1 + sh1;
        float y2 = (lane < 16) ? (g_a[base + 64 + lane] * sc2 + sh2) : -3.4e38f;

        float mx = fmaxf(fmaxf(y0, y1), y2);
#pragma unroll
        for (int o = 16; o > 0; o >>= 1) mx = fmaxf(mx, __shfl_xor_sync(0xffffffffu, mx, o));

        float e0 = expf(y0 - mx);
        float e1 = expf(y1 - mx);
        float e2 = (lane < 16) ? expf(y2 - mx) : 0.f;
        float s  = e0 + e1 + e2;
#pragma unroll
        for (int o = 16; o > 0; o >>= 1) s += __shfl_xor_sync(0xffffffffu, s, o);

        float inv = 1.f / s;
        float p0 = e0 * inv, p1 = e1 * inv;
        g_a[base + lane]      = p0;
        g_a[base + 32 + lane] = p1;
        atomicAdd(&s_asum[lane],      p0);
        atomicAdd(&s_asum[lane + 32], p1);
    }
    __syncthreads();
    if (tid < KK) atomicAdd(&g_asum[batch * KK + tid], s_asum[tid]);
}

// ------------------------- K3: mma.sync GEMM  V[b][d][k] = sum_n X[n,d] P[n,k] -----
// CTA: batch b, 64-d tile, all 64 k, n-loop in chunks of 64 tokens.
// A = Xt[d][n] (row-major, n contiguous), B = Pt[k][n] (col-major op = n contiguous).
// hi/lo bf16 split, 3 terms: Ah*Bh + Al*Bh + Ah*Bl, fp32 accum.
// Warp layout: 8 warps = 2(m: 32 d each) x 4(n: 16 k each).
#define XSTRIDE 72
__global__ __launch_bounds__(256) void k3_mma(const float* __restrict__ x) {
    __shared__ __align__(16) uint16_t XtH[64 * XSTRIDE], XtL[64 * XSTRIDE];
    __shared__ __align__(16) uint16_t PtH[64 * XSTRIDE], PtL[64 * XSTRIDE];

    const int tid  = threadIdx.x;
    const int lane = tid & 31;
    const int w    = tid >> 5;
    const int b    = blockIdx.y;
    const int d0   = blockIdx.x * 64;

    // fill-phase indices
    const int fx_d = (w & 1) * 32 + lane;   // d row this thread fills (X)
    const int fx_s = w >> 1;                // n stripe base (X): n = fx_s + 4j
    const int fp_k = tid & 63;              // k row this thread fills (P)
    const int fp_q = tid >> 6;              // n quarter (P): n = 16*fp_q + j

    // compute-phase indices
    const int wm = w >> 2;                  // 0..1 (32 d each)
    const int wn = w & 3;                   // 0..3 (16 k each)

    float acc[2][2][4] = {};                // [m16 tile][n8 tile][frag]

    const float* xb = x + (size_t)b * NN * DD + d0;
    const float* pb = g_a + (size_t)b * NN * CC;

    const uint32_t xh = smem_u32(XtH), xl = smem_u32(XtL);
    const uint32_t ph = smem_u32(PtH), pl = smem_u32(PtL);

    for (int n0 = 0; n0 < NN; n0 += 64) {
        // ---- X fill: coalesced LDG (consecutive d per warp), transpose into Xt[d][n]
#pragma unroll
        for (int j = 0; j < 16; ++j) {
            int n = fx_s + 4 * j;
            float v = xb[(size_t)(n0 + n) * DD + fx_d];
            uint16_t h, l;
            split_bf16(v, h, l);
            XtH[fx_d * XSTRIDE + n] = h;
            XtL[fx_d * XSTRIDE + n] = l;
        }
        // ---- P fill: coalesced LDG (consecutive k per warp), transpose into Pt[k][n]
#pragma unroll
        for (int j = 0; j < 16; ++j) {
            int n = fp_q * 16 + j;
            float v = pb[(size_t)(n0 + n) * CC + fp_k];
            uint16_t h, l;
            split_bf16(v, h, l);
            PtH[fp_k * XSTRIDE + n] = h;
            PtL[fp_k * XSTRIDE + n] = l;
        }
        __syncthreads();

        // ---- compute: 4 k-steps of 16 tokens
#pragma unroll
        for (int s = 0; s < 4; ++s) {
            const uint32_t coloff = ((lane >> 4) * 8 + 16 * s) * 2;
            uint32_t ah[2][4], al[2][4], bh[4], bl[4];
#pragma unroll
            for (int mt = 0; mt < 2; ++mt) {
                uint32_t ro = (uint32_t)(32 * wm + 16 * mt + (lane & 15)) * (XSTRIDE * 2);
                LDSM_X4(ah[mt][0], ah[mt][1], ah[mt][2], ah[mt][3], xh + ro + coloff);
                LDSM_X4(al[mt][0], al[mt][1], al[mt][2], al[mt][3], xl + ro + coloff);
            }
            {
                uint32_t ro = (uint32_t)(16 * wn + (lane & 15)) * (XSTRIDE * 2);
                LDSM_X4(bh[0], bh[1], bh[2], bh[3], ph + ro + coloff);
                LDSM_X4(bl[0], bl[1], bl[2], bl[3], pl + ro + coloff);
            }
            // B frags: n-tile0 = {r0, r2}  (k rows 0-7), n-tile1 = {r1, r3} (k rows 8-15)
#pragma unroll
            for (int mt = 0; mt < 2; ++mt) {
                MMA_BF16(acc[mt][0], ah[mt], bh[0], bh[2]);
                MMA_BF16(acc[mt][0], al[mt], bh[0], bh[2]);
                MMA_BF16(acc[mt][0], ah[mt], bl[0], bl[2]);
                MMA_BF16(acc[mt][1], ah[mt], bh[1], bh[3]);
                MMA_BF16(acc[mt][1], al[mt], bh[1], bh[3]);
                MMA_BF16(acc[mt][1], ah[mt], bl[1], bl[3]);
            }
        }
        __syncthreads();
    }

    // ---- epilogue: frag (row g, col 2t) -> g_v[b][d][k]
    const int g  = lane >> 2;
    const int t2 = lane & 3;
#pragma unroll
    for (int mt = 0; mt < 2; ++mt) {
        int drow = d0 + 32 * wm + 16 * mt + g;
#pragma unroll
        for (int nt = 0; nt < 2; ++nt) {
            int kc = 16 * wn + 8 * nt + 2 * t2;
            *(float2*)(g_v + ((size_t)b * DD + drow) * KK + kc) =
                make_float2(acc[mt][nt][0], acc[mt][nt][1]);
            *(float2*)(g_v + ((size_t)b * DD + drow + 8) * KK + kc) =
                make_float2(acc[mt][nt][2], acc[mt][nt][3]);
        }
    }
}

// ------------------------- K4: residual subtract + per-(b,k) sumsq (layout [b][d][k])
__global__ __launch_bounds__(256) void k4_resid(const float* __restrict__ c2) {
    __shared__ float s_ss[KK];
    __shared__ float s_as[KK];
    const int b = blockIdx.x;
    const int tid = threadIdx.x;
    const int lane = tid & 31;

    if (tid < KK) { s_ss[tid] = 0.f; s_as[tid] = g_asum[b * KK + tid]; }
    __syncthreads();

    float* vb = g_v + (size_t)b * DD * KK;
    const int koff = (tid & 15) * 4;
    const float a0 = s_as[koff], a1 = s_as[koff + 1], a2 = s_as[koff + 2], a3 = s_as[koff + 3];
    float lss0 = 0.f, lss1 = 0.f, lss2 = 0.f, lss3 = 0.f;

#pragma unroll 4
    for (int it = 0; it < 32; ++it) {
        int j = tid + it * 256;            // float4 index; k slice invariant per thread
        int dloc = j >> 4;
        float4 v = *(float4*)(vb + (size_t)j * 4);
        float4 cc = *(const float4*)(c2 + (size_t)dloc * KK + koff);
        float r0 = v.x - a0 * cc.x;
        float r1 = v.y - a1 * cc.y;
        float r2 = v.z - a2 * cc.z;
        float r3 = v.w - a3 * cc.w;
        *(float4*)(vb + (size_t)j * 4) = make_float4(r0, r1, r2, r3);
        lss0 += r0 * r0; lss1 += r1 * r1; lss2 += r2 * r2; lss3 += r3 * r3;
    }
    lss0 += __shfl_xor_sync(0xffffffffu, lss0, 16);
    lss1 += __shfl_xor_sync(0xffffffffu, lss1, 16);
    lss2 += __shfl_xor_sync(0xffffffffu, lss2, 16);
    lss3 += __shfl_xor_sync(0xffffffffu, lss3, 16);
    if (lane < 16) {
        atomicAdd(&s_ss[koff + 0], lss0);
        atomicAdd(&s_ss[koff + 1], lss1);
        atomicAdd(&s_ss[koff + 2], lss2);
        atomicAdd(&s_ss[koff + 3], lss3);
    }
    __syncthreads();
    if (tid < KK) g_S[b * KK + tid] = s_ss[tid];
}

// ------------------------- K5: per-batch norm factors ------------------------------
__global__ void k5_norm() {
    const int b = blockIdx.x;
    const int k = threadIdx.x;   // 64 threads
    float S    = g_S[b * KK + k];
    float norm = sqrtf(S);
    float inv  = 1.f / fmaxf(norm, 1e-12f);
    float c    = S * inv * inv;
#pragma unroll
    for (int o = 16; o > 0; o >>= 1) c += __shfl_xor_sync(0xffffffffu, c, o);
    __shared__ float sh[2];
    if ((k & 31) == 0) sh[k >> 5] = c;
    __syncthreads();
    float g = sqrtf(sh[0] + sh[1]);
    g_f[b * KK + k] = inv / fmaxf(g, 1e-12f);
}

// ------------------------- K6: out[b][d*K+k] = g_v[b][d][k] * f[b][k] --------------
__global__ __launch_bounds__(256) void k6_write(float* __restrict__ out) {
    __shared__ float s_f[KK];
    const int b = blockIdx.y;
    const int tid = threadIdx.x;
    if (tid < KK) s_f[tid] = g_f[b * KK + tid];
    __syncthreads();

    const float* vb = g_v + (size_t)b * DD * KK;
    float* ob = out + (size_t)b * DD * KK;
    const int koff = (tid & 15) * 4;
    const float f0 = s_f[koff], f1 = s_f[koff + 1], f2 = s_f[koff + 2], f3 = s_f[koff + 3];

#pragma unroll
    for (int it = 0; it < 4; ++it) {
        int j = blockIdx.x * 1024 + tid + it * 256;   // float4 index
        float4 v = *(const float4*)(vb + (size_t)j * 4);
        *(float4*)(ob + (size_t)j * 4) = make_float4(v.x * f0, v.y * f1, v.z * f2, v.w * f3);
    }
}

// ------------------------- launch -------------------------------------------------
extern "C" void kernel_launch(void* const* d_in, const int* in_sizes, int n_in,
                              void* d_out, int out_size) {
    const float* x        = (const float*)d_in[0];
    const float* clusters = (const float*)d_in[1];
    const float* clusters2= (const float*)d_in[2];
    const float* bnw      = (const float*)d_in[3];
    const float* bnb      = (const float*)d_in[4];
    float* out            = (float*)d_out;

    k0_zero   <<<16, 256>>>();
    k1_gemm1  <<<MROWS / 128, 256>>>(x, clusters);
    k2_softmax<<<MROWS / 128, 256>>>(bnw, bnb);
    k3_mma    <<<dim3(DD / 64, BB), 256>>>(x);
    k4_resid  <<<BB, 256>>>(clusters2);
    k5_norm   <<<BB, 64>>>();
    k6_write  <<<dim3(8, BB), 256>>>(out);
}